// round 5
// baseline (speedup 1.0000x reference)
#include <cuda_runtime.h>
#include <cstdint>

#define T_LEN   730
#define B_LEN   1000
#define LENF    15
#define NEARZERO 1e-5f

#define SCAN_BLOCKS 125          // blocks 0..124: scan (64 threads each, 8000 chains)
#define NBLK        126          // + block 125: unit hydrograph
#define BLK_T       512
#define UG 10
#define NGROUPS 73               // 73*10 = 730

// Scratch (device globals: allocation-free)
__device__ float g_qsurf[T_LEN * B_LEN];
__device__ float g_qgw  [T_LEN * B_LEN];
__device__ float g_uh   [B_LEN * LENF];

// grid barrier state (sense-reversing; self-resetting across graph replays)
__device__ unsigned g_count = 0;
__device__ unsigned g_sense = 0;

__device__ __forceinline__ void grid_barrier() {
    __syncthreads();
    if (threadIdx.x == 0) {
        volatile unsigned* vs = &g_sense;
        unsigned s = *vs;
        __threadfence();
        if (atomicAdd(&g_count, 1u) == NBLK - 1u) {
            g_count = 0;
            __threadfence();
            *vs = s ^ 1u;
        } else {
            while (*vs == s) { }
            __threadfence();
        }
    }
    __syncthreads();
}

__device__ __forceinline__ float f_sqrt_approx(float x) {
    float r; asm("sqrt.approx.f32 %0, %1;" : "=f"(r) : "f"(x)); return r;
}
__device__ __forceinline__ float f_ex2(float x) {
    float r; asm("ex2.approx.f32 %0, %1;" : "=f"(r) : "f"(x)); return r;
}
__device__ __forceinline__ float shx(float v, int m) {
    return __shfl_xor_sync(0xffffffffu, v, m);
}

// ---------------------------------------------------------------------------
// unit hydrograph for one basin
// ---------------------------------------------------------------------------
__device__ void uh_for_basin(const float* __restrict__ raw, int b) {
    float ra = raw[b * 34 + 32] * 2.9f;
    float rb = raw[b * 34 + 33] * 6.5f;
    float aa    = fmaxf(ra, 0.0f) + 0.1f;
    float theta = fmaxf(rb, 0.0f) + 0.5f;
    float lg   = lgammaf(aa);
    float lth  = logf(theta);
    float ivth = 1.0f / theta;
    float w[LENF];
    float s = 0.0f;
#pragma unroll
    for (int k = 0; k < LENF; ++k) {
        float t = (float)k + 0.5f;
        float lw = (aa - 1.0f) * logf(t) - t * ivth - lg - aa * lth;
        w[k] = expf(lw);
        s += w[k];
    }
    float inv = 1.0f / s;
#pragma unroll
    for (int k = 0; k < LENF; ++k)
        g_uh[b * LENF + k] = w[k] * inv;
}

// ---------------------------------------------------------------------------
// Fused persistent kernel: phase 1 = scan (+uh), grid barrier, phase 2 = conv
// ---------------------------------------------------------------------------
__global__ void __launch_bounds__(BLK_T) fused_kernel(
    const float* __restrict__ x,      // (T,B,2)
    const float* __restrict__ raw,    // (B,34)
    float* __restrict__ out)          // (T,B,6)
{
    const int tid = threadIdx.x;

    // ===================== Phase 1 =====================
    if (blockIdx.x == SCAN_BLOCKS) {
        // unit hydrograph block
        for (int b = tid; b < B_LEN; b += BLK_T) uh_for_basin(raw, b);
    } else if (tid < 64) {
        // ---- abcd scan: 1 chain/thread, 8 lanes per basin ----
        int g  = blockIdx.x * 64 + tid;   // 0..7999
        int b  = g >> 3;
        int m  = g & 7;

        float a   = fmaf(raw[b*34 +      m], 0.9f, 0.1f);
        float bb  = fmaf(raw[b*34 +  8 + m], 450.0f, 50.0f);
        float c   = raw[b*34 + 16 + m];
        float d   = fmaf(raw[b*34 + 24 + m], 0.89f, 0.01f);

        float inv2a  = 0.5f / a;
        float binv2a = bb * inv2a;
        float boa    = bb / a;
        float nl2eob = -1.44269504088896f / bb;
        float onemc  = 1.0f - c;
        float inv1pd = 1.0f / (1.0f + d);

        float S = 50.0f, G = 10.0f;

        bool is1 = (m == 1), is2 = (m == 2), is3 = (m == 3), is4 = (m == 4);
        bool doStore = (m < 5);
        float* sp;
        int sstride;
        if      (m == 0) { sp = g_qsurf + b;       sstride = B_LEN; }
        else if (m == 1) { sp = g_qgw   + b;       sstride = B_LEN; }
        else if (m == 2) { sp = out + b * 6 + 3;   sstride = 6 * B_LEN; }
        else if (m == 3) { sp = out + b * 6 + 4;   sstride = 6 * B_LEN; }
        else if (m == 4) { sp = out + b * 6 + 5;   sstride = 6 * B_LEN; }
        else             { sp = g_qsurf + b;       sstride = B_LEN; }

        const float2* __restrict__ xv = (const float2*)x;

        // 3-deep pipelined reduction state
        float s1qs=0.f, s1qg=0.f, s1ae=0.f, s1s=0.f, s1g=0.f;
        float s2qs=0.f, s2qg=0.f, s2ae=0.f, s2s=0.f, s2g=0.f;

        float2 cur[UG], nxt[UG];

#define BODY(PV, PETV, DOSTORE) do {                                     \
        float p   = (PV);                                                \
        float pet = (PETV);                                              \
        float W    = p + S;                                              \
        float term = fmaf(W, inv2a, binv2a);                             \
        float arg  = fmaxf(fmaf(term, term, -(W * boa)), NEARZERO);      \
        float Y    = term - f_sqrt_approx(arg);                          \
        float Snew = Y * f_ex2(pet * nl2eob);                            \
        float avail = W - Y;                                             \
        float vqs  = onemc * avail;                                      \
        float Gnew = fmaf(c, avail, G) * inv1pd;                         \
        float vqg  = d * Gnew;                                           \
        float vae  = Y - Snew;                                           \
        S = Snew; G = Gnew;                                              \
        /* stage-3 shfls (values of step t-2) */                         \
        float r3a = shx(s2qs, 4), r3b = shx(s2qg, 4), r3c = shx(s2ae, 4);\
        float r3d = shx(s2s , 4), r3e = shx(s2g , 4);                    \
        /* stage-2 shfls (step t-1) */                                   \
        float r2a = shx(s1qs, 2), r2b = shx(s1qg, 2), r2c = shx(s1ae, 2);\
        float r2d = shx(s1s , 2), r2e = shx(s1g , 2);                    \
        /* stage-1 shfls (step t) */                                     \
        float r1a = shx(vqs, 1), r1b = shx(vqg, 1), r1c = shx(vae, 1);   \
        float r1d = shx(Snew, 1), r1e = shx(Gnew, 1);                    \
        /* finalize step t-2 */                                          \
        float fqs = s2qs + r3a, fqg = s2qg + r3b, fae = s2ae + r3c;      \
        float fs  = s2s  + r3d, fg  = s2g  + r3e;                        \
        /* advance pipeline */                                           \
        s2qs = s1qs + r2a; s2qg = s1qg + r2b; s2ae = s1ae + r2c;         \
        s2s  = s1s  + r2d; s2g  = s1g  + r2e;                            \
        s1qs = vqs + r1a; s1qg = vqg + r1b; s1ae = vae + r1c;            \
        s1s  = Snew + r1d; s1g = Gnew + r1e;                             \
        if (DOSTORE) {                                                   \
            float v = fqs;                                               \
            if (is1) v = fqg;                                            \
            if (is2) v = fae;                                            \
            if (is3) v = fs;                                             \
            if (is4) v = fg;                                             \
            if (doStore) *sp = v * 0.125f;                               \
            sp += sstride;                                               \
        }                                                                \
    } while (0)

        // group 0 (peeled: first 2 steps fill the pipeline, no store)
#pragma unroll
        for (int i = 0; i < UG; ++i) cur[i] = __ldg(xv + i * B_LEN + b);
        {
            const float2* base = xv + UG * B_LEN + b;
#pragma unroll
            for (int i = 0; i < UG; ++i) nxt[i] = __ldg(base + i * B_LEN);
        }
        BODY(cur[0].x, cur[0].y, false);
        BODY(cur[1].x, cur[1].y, false);
#pragma unroll
        for (int i = 2; i < UG; ++i) BODY(cur[i].x, cur[i].y, true);
#pragma unroll
        for (int i = 0; i < UG; ++i) cur[i] = nxt[i];

        for (int gi = 1; gi < NGROUPS; ++gi) {
            if (gi < NGROUPS - 1) {
                const float2* base = xv + (gi + 1) * UG * B_LEN + b;
#pragma unroll
                for (int i = 0; i < UG; ++i) nxt[i] = __ldg(base + i * B_LEN);
            }
#pragma unroll
            for (int i = 0; i < UG; ++i) BODY(cur[i].x, cur[i].y, true);
            if (gi < NGROUPS - 1) {
#pragma unroll
                for (int i = 0; i < UG; ++i) cur[i] = nxt[i];
            }
        }
#undef BODY

        // epilogue: drain rows 728, 729
#pragma unroll
        for (int e = 0; e < 2; ++e) {
            float fqs = s2qs + shx(s2qs, 4);
            float fqg = s2qg + shx(s2qg, 4);
            float fae = s2ae + shx(s2ae, 4);
            float fs  = s2s  + shx(s2s , 4);
            float fg  = s2g  + shx(s2g , 4);
            float v = fqs;
            if (is1) v = fqg;
            if (is2) v = fae;
            if (is3) v = fs;
            if (is4) v = fg;
            if (doStore) *sp = v * 0.125f;
            sp += sstride;
            s2qs = s1qs + shx(s1qs, 2);
            s2qg = s1qg + shx(s1qg, 2);
            s2ae = s1ae + shx(s1ae, 2);
            s2s  = s1s  + shx(s1s , 2);
            s2g  = s1g  + shx(s1g , 2);
        }
    }

    // ===================== barrier =====================
    grid_barrier();

    // ===================== Phase 2: conv (R1-proven TPER=5 form) ============
    const int nItems = (T_LEN / 5) * B_LEN;   // 146000
    for (int item = blockIdx.x * BLK_T + tid; item < nItems; item += NBLK * BLK_T) {
        int b  = item % B_LEN;
        int t0 = (item / B_LEN) * 5;

        float uh[LENF];
#pragma unroll
        for (int k = 0; k < LENF; ++k) uh[k] = __ldg(&g_uh[b * LENF + k]);

        float qs1[LENF - 1 + 5];
        float qs2[LENF - 1 + 5];
#pragma unroll
        for (int i = 0; i < LENF - 1 + 5; ++i) {
            int tt = t0 - (LENF - 1) + i;
            bool ok = (tt >= 0);
            qs1[i] = ok ? __ldg(&g_qsurf[tt * B_LEN + b]) : 0.0f;
            qs2[i] = ok ? __ldg(&g_qgw  [tt * B_LEN + b]) : 0.0f;
        }
#pragma unroll
        for (int j = 0; j < 5; ++j) {
            float a1 = 0.0f, a2 = 0.0f;
#pragma unroll
            for (int k = 0; k < LENF; ++k) {
                a1 = fmaf(uh[k], qs1[LENF - 1 + j - k], a1);
                a2 = fmaf(uh[k], qs2[LENF - 1 + j - k], a2);
            }
            float* o = out + (t0 + j) * (6 * B_LEN) + b * 6;
            o[0] = a1 + a2;   // routed Qsim (conv is linear)
            o[1] = a1;        // routed Qsurf
            o[2] = a2;        // routed Qgw
        }
    }
}

// ---------------------------------------------------------------------------
extern "C" void kernel_launch(void* const* d_in, const int* in_sizes, int n_in,
                              void* d_out, int out_size) {
    const float* x   = (const float*)d_in[0];   // (730,1000,2)
    const float* raw = (const float*)d_in[1];   // (1000,34)
    float* out = (float*)d_out;                 // (730,1000,6)

    fused_kernel<<<NBLK, BLK_T>>>(x, raw, out);
}

// round 7
// speedup vs baseline: 1.1358x; 1.1358x over previous
#include <cuda_runtime.h>
#include <cstdint>

#define T_LEN   730
#define B_LEN   1000
#define LENF    15
#define NEARZERO 1e-5f

#define SCAN_BLOCKS 125          // blocks 0..124: scan; block 125: unit hydrograph
#define NBLK        126
#define BLK_T       512
#define UG 10
#define NGROUPS 73               // 73*10 = 730

// smem reduction buffer strides (floats)
#define LANE_S 1
#define Q_S    8
#define BAS_S  44                // 8 lanes*4B padded to 176B (16B aligned)
#define STEP_S (BAS_S * 8)      // 352
#define SLOT_S (STEP_S * UG)    // 3520
#define SRED_FLOATS (2 * SLOT_S)

// Scratch (device globals: allocation-free)
__device__ float g_qsurf[T_LEN * B_LEN];
__device__ float g_qgw  [T_LEN * B_LEN];
__device__ float g_uh   [B_LEN * LENF];

// grid barrier state (sense-reversing; self-resetting across graph replays)
__device__ unsigned g_count = 0;
__device__ unsigned g_sense = 0;

__device__ __forceinline__ void grid_barrier() {
    __syncthreads();
    if (threadIdx.x == 0) {
        volatile unsigned* vs = &g_sense;
        unsigned s = *vs;
        __threadfence();
        if (atomicAdd(&g_count, 1u) == NBLK - 1u) {
            g_count = 0;
            __threadfence();
            *vs = s ^ 1u;
        } else {
            while (*vs == s) { }
            __threadfence();
        }
    }
    __syncthreads();
}

__device__ __forceinline__ float f_sqrt_approx(float x) {
    float r; asm("sqrt.approx.f32 %0, %1;" : "=f"(r) : "f"(x)); return r;
}
__device__ __forceinline__ float f_ex2(float x) {
    float r; asm("ex2.approx.f32 %0, %1;" : "=f"(r) : "f"(x)); return r;
}

// named barriers: producers arrive (non-blocking), consumers sync (blocking).
// total arrivals per phase = 64 (arrive) + 64 (sync) = 128.
#define BAR_SYNC(id)   asm volatile("bar.sync %0, 128;"   :: "r"(id) : "memory")
#define BAR_ARRIVE(id) asm volatile("bar.arrive %0, 128;" :: "r"(id) : "memory")
// ids: A (batch ready) = 1 + slot; B (slot free) = 3 + slot

// ---------------------------------------------------------------------------
// unit hydrograph for one basin
// ---------------------------------------------------------------------------
__device__ void uh_for_basin(const float* __restrict__ raw, int b) {
    float ra = raw[b * 34 + 32] * 2.9f;
    float rb = raw[b * 34 + 33] * 6.5f;
    float aa    = fmaxf(ra, 0.0f) + 0.1f;
    float theta = fmaxf(rb, 0.0f) + 0.5f;
    float lg   = lgammaf(aa);
    float lth  = logf(theta);
    float ivth = 1.0f / theta;
    float w[LENF];
    float s = 0.0f;
#pragma unroll
    for (int k = 0; k < LENF; ++k) {
        float t = (float)k + 0.5f;
        float lw = (aa - 1.0f) * logf(t) - t * ivth - lg - aa * lth;
        w[k] = expf(lw);
        s += w[k];
    }
    float inv = 1.0f / s;
#pragma unroll
    for (int k = 0; k < LENF; ++k)
        g_uh[b * LENF + k] = w[k] * inv;
}

// ---------------------------------------------------------------------------
// Fused persistent kernel.
// Phase 1 (blocks 0..124): warps 0,1 = producers (abcd recurrence, 1 chain per
// thread, 8 lanes/basin, results to smem); warps 2,3 = consumers (sum 8 lanes,
// store means). Block 125 = unit hydrograph. Then grid barrier, then conv.
// ---------------------------------------------------------------------------
__global__ void __launch_bounds__(BLK_T) fused_kernel(
    const float* __restrict__ x,      // (T,B,2)
    const float* __restrict__ raw,    // (B,34)
    float* __restrict__ out)          // (T,B,6)
{
    __shared__ __align__(16) float sred[SRED_FLOATS];
    const int tid = threadIdx.x;

    if (blockIdx.x == SCAN_BLOCKS) {
        for (int b = tid; b < B_LEN; b += BLK_T) uh_for_basin(raw, b);
    } else if (tid < 64) {
        // =================== producers: pure recurrence ===================
        int bl = tid >> 3;                        // basin-local 0..7
        int m  = tid & 7;                         // channel
        int b  = blockIdx.x * 8 + bl;             // global basin

        float a   = fmaf(raw[b*34 +      m], 0.9f, 0.1f);
        float bb  = fmaf(raw[b*34 +  8 + m], 450.0f, 50.0f);
        float c   = raw[b*34 + 16 + m];
        float d   = fmaf(raw[b*34 + 24 + m], 0.89f, 0.01f);

        float inv2a  = 0.5f / a;
        float binv2a = bb * inv2a;
        float boa    = bb / a;
        float nl2eob = -1.44269504088896f / bb;
        float onemc  = 1.0f - c;
        float inv1pd = 1.0f / (1.0f + d);

        float S = 50.0f, G = 10.0f;

        float* my = sred + bl * BAS_S + m;        // + q*Q_S + slot/step offsets

        const float2* __restrict__ xv = (const float2*)x;
        float2 cur[UG], nxt[UG];
#pragma unroll
        for (int i = 0; i < UG; ++i) cur[i] = __ldg(xv + i * B_LEN + b);

        for (int gi = 0; gi < NGROUPS; ++gi) {
            if (gi < NGROUPS - 1) {
                const float2* base = xv + (gi + 1) * UG * B_LEN + b;
#pragma unroll
                for (int i = 0; i < UG; ++i) nxt[i] = __ldg(base + i * B_LEN);
            }
            int slot = gi & 1;
            if (gi >= 2) BAR_SYNC(3 + slot);      // wait consumers freed slot
            float* sb = my + slot * SLOT_S;
#pragma unroll
            for (int i = 0; i < UG; ++i) {
                float p   = cur[i].x;
                float pet = cur[i].y;
                float W    = p + S;
                float term = fmaf(W, inv2a, binv2a);
                float arg  = fmaxf(fmaf(term, term, -(W * boa)), NEARZERO);
                float Y    = term - f_sqrt_approx(arg);
                float Snew = Y * f_ex2(pet * nl2eob);
                float avail = W - Y;
                float vqs  = onemc * avail;
                float Gnew = fmaf(c, avail, G) * inv1pd;
                float vqg  = d * Gnew;
                float vae  = Y - Snew;
                S = Snew;
                G = Gnew;
                float* sl = sb + i * STEP_S;
                sl[0 * Q_S] = vqs;
                sl[1 * Q_S] = vqg;
                sl[2 * Q_S] = vae;
                sl[3 * Q_S] = Snew;
                sl[4 * Q_S] = Gnew;
            }
            BAR_ARRIVE(1 + slot);                 // batch ready
            if (gi < NGROUPS - 1) {
#pragma unroll
                for (int i = 0; i < UG; ++i) cur[i] = nxt[i];
            }
        }
    } else if (tid < 128) {
        // =================== consumers: reduce + store ===================
        int rtid = tid - 64;
        bool active = (rtid < 40);
        int g8 = rtid / 5;                        // basin-local
        int q  = active ? (rtid % 5) : 0;
        int b  = blockIdx.x * 8 + (active ? g8 : 0);

        float* dst;
        int dstride;
        if      (q == 0) { dst = g_qsurf + b;     dstride = B_LEN; }
        else if (q == 1) { dst = g_qgw   + b;     dstride = B_LEN; }
        else if (q == 2) { dst = out + b*6 + 3;   dstride = 6 * B_LEN; }
        else if (q == 3) { dst = out + b*6 + 4;   dstride = 6 * B_LEN; }
        else             { dst = out + b*6 + 5;   dstride = 6 * B_LEN; }

        const float* src0 = sred + (active ? g8 : 0) * BAS_S + q * Q_S;

        for (int gi = 0; gi < NGROUPS; ++gi) {
            int slot = gi & 1;
            BAR_SYNC(1 + slot);                   // wait batch ready
            if (active) {
                const float* sb = src0 + slot * SLOT_S;
#pragma unroll
                for (int i = 0; i < UG; ++i) {
                    const float4* p4 = (const float4*)(sb + i * STEP_S);
                    float4 r0 = p4[0];
                    float4 r1 = p4[1];
                    float s = ((r0.x + r0.y) + (r0.z + r0.w))
                            + ((r1.x + r1.y) + (r1.z + r1.w));
                    *dst = s * 0.125f;
                    dst += dstride;
                }
            }
            BAR_ARRIVE(3 + slot);                 // slot free
        }
    }
    // warps 4..15 (and uh block) fall through to the grid barrier

    // ===================== barrier =====================
    grid_barrier();

    // ===================== Phase 2: conv (TPER=5) =====================
    const int nItems = (T_LEN / 5) * B_LEN;   // 146000
    for (int item = blockIdx.x * BLK_T + tid; item < nItems; item += NBLK * BLK_T) {
        int b  = item % B_LEN;
        int t0 = (item / B_LEN) * 5;

        float uh[LENF];
#pragma unroll
        for (int k = 0; k < LENF; ++k) uh[k] = __ldg(&g_uh[b * LENF + k]);

        float qs1[LENF - 1 + 5];
        float qs2[LENF - 1 + 5];
#pragma unroll
        for (int i = 0; i < LENF - 1 + 5; ++i) {
            int tt = t0 - (LENF - 1) + i;
            bool ok = (tt >= 0);
            qs1[i] = ok ? __ldg(&g_qsurf[tt * B_LEN + b]) : 0.0f;
            qs2[i] = ok ? __ldg(&g_qgw  [tt * B_LEN + b]) : 0.0f;
        }
#pragma unroll
        for (int j = 0; j < 5; ++j) {
            float a1 = 0.0f, a2 = 0.0f;
#pragma unroll
            for (int k = 0; k < LENF; ++k) {
                a1 = fmaf(uh[k], qs1[LENF - 1 + j - k], a1);
                a2 = fmaf(uh[k], qs2[LENF - 1 + j - k], a2);
            }
            float* o = out + (t0 + j) * (6 * B_LEN) + b * 6;
            o[0] = a1 + a2;   // routed Qsim (conv is linear)
            o[1] = a1;        // routed Qsurf
            o[2] = a2;        // routed Qgw
        }
    }
}

// ---------------------------------------------------------------------------
extern "C" void kernel_launch(void* const* d_in, const int* in_sizes, int n_in,
                              void* d_out, int out_size) {
    const float* x   = (const float*)d_in[0];   // (730,1000,2)
    const float* raw = (const float*)d_in[1];   // (1000,34)
    float* out = (float*)d_out;                 // (730,1000,6)

    fused_kernel<<<NBLK, BLK_T>>>(x, raw, out);
}